// round 3
// baseline (speedup 1.0000x reference)
#include <cuda_runtime.h>
#include <cuda_bf16.h>

// ---------------------------------------------------------------------------
// QuantumLayerVQC: out[b] = e(b)^T M e(b)
//   e(b) = [cos(x0/2),sin(x0/2)] (x) [cos(x1/2),sin(x1/2)] (x) [cos(x2/2),sin(x2/2)]
//   M    = sum_k s_k (Re U_k Re U_k^T + Im U_k Im U_k^T), s_k = +1 if (k & 4)==0 else -1
//   U    = fixed 8x8 unitary from the 3 variational layers (weights w[3,3,2]).
// Qubit q <-> bitmask (4 >> q): q0->4, q1->2, q2->1 (matches [B,q0,q1,q2] layout).
// ---------------------------------------------------------------------------

__device__ __forceinline__ float2 cmulf(float2 a, float2 b) {
    return make_float2(a.x * b.x - a.y * b.y, a.x * b.y + a.y * b.x);
}

template <int M>
__device__ __forceinline__ void ry_g(float2 st[8], float theta) {
    float s, c;
    sincosf(0.5f * theta, &s, &c);   // precise: once per block, off hot path
#pragma unroll
    for (int k = 0; k < 8; k++) {
        if (!(k & M)) {
            float2 a = st[k], b = st[k | M];
            st[k]     = make_float2(c * a.x - s * b.x, c * a.y - s * b.y);
            st[k | M] = make_float2(s * a.x + c * b.x, s * a.y + c * b.y);
        }
    }
}

template <int M>
__device__ __forceinline__ void rz_g(float2 st[8], float phi) {
    float s, c;
    sincosf(0.5f * phi, &s, &c);
    float2 p0 = make_float2(c, -s);  // exp(-i phi/2) on bit=0
    float2 p1 = make_float2(c,  s);  // exp(+i phi/2) on bit=1
#pragma unroll
    for (int k = 0; k < 8; k++) st[k] = cmulf(st[k], (k & M) ? p1 : p0);
}

template <int CM, int TM>
__device__ __forceinline__ void cnot_g(float2 st[8]) {
#pragma unroll
    for (int k = 0; k < 8; k++) {
        if ((k & CM) && !(k & TM)) {
            float2 t = st[k];
            st[k] = st[k | TM];
            st[k | TM] = t;
        }
    }
}

__device__ __forceinline__ float qform(const float* __restrict__ sM, float4 r) {
    float c0, s0, c1, s1, c2, s2;
    __sincosf(0.5f * r.x, &s0, &c0);
    __sincosf(0.5f * r.y, &s1, &c1);
    __sincosf(0.5f * r.z, &s2, &c2);

    const float t00 = c1 * c2, t01 = c1 * s2, t10 = s1 * c2, t11 = s1 * s2;
    float e[8];
    e[0] = c0 * t00; e[1] = c0 * t01; e[2] = c0 * t10; e[3] = c0 * t11;
    e[4] = s0 * t00; e[5] = s0 * t01; e[6] = s0 * t10; e[7] = s0 * t11;

    float acc = 0.f;
#pragma unroll
    for (int i = 0; i < 8; i++) {
        float v = 0.f;
#pragma unroll
        for (int j = 0; j < 8; j++) v = fmaf(sM[i * 8 + j], e[j], v);
        acc = fmaf(e[i], v, acc);
    }
    return acc;
}

__global__ __launch_bounds__(256) void vqc_kernel(
    const float* __restrict__ x,   // [n, 8]
    const float* __restrict__ w,   // [3, 3, 2]
    float* __restrict__ out,       // [n]
    int n)
{
    __shared__ float2 sU[8][8];    // U[k][col]
    __shared__ float  sM[64];      // quadratic-form matrix

    const int tid = threadIdx.x;

    // --- Phase 1: threads 0..7 each simulate one basis column of U ----------
    if (tid < 8) {
        float2 st[8];
#pragma unroll
        for (int k = 0; k < 8; k++) st[k] = make_float2(0.f, 0.f);
        st[tid] = make_float2(1.f, 0.f);

#pragma unroll
        for (int l = 0; l < 3; l++) {
            const float* wl = w + l * 6;   // w[l, i, {ry,rz}]
            ry_g<4>(st, wl[0]); rz_g<4>(st, wl[1]);   // qubit 0
            ry_g<2>(st, wl[2]); rz_g<2>(st, wl[3]);   // qubit 1
            ry_g<1>(st, wl[4]); rz_g<1>(st, wl[5]);   // qubit 2
            cnot_g<4, 2>(st);                          // CNOT(0,1)
            cnot_g<2, 1>(st);                          // CNOT(1,2)
        }
#pragma unroll
        for (int k = 0; k < 8; k++) sU[k][tid] = st[k];
    }
    __syncthreads();

    // --- Phase 2: threads 0..63 build M -------------------------------------
    if (tid < 64) {
        const int i = tid >> 3, j = tid & 7;
        float m = 0.f;
#pragma unroll
        for (int k = 0; k < 8; k++) {
            float t = sU[k][i].x * sU[k][j].x + sU[k][i].y * sU[k][j].y;
            m += (k & 4) ? -t : t;
        }
        sM[tid] = m;
    }
    __syncthreads();

    // --- Phase 3: grid-stride, 2 rows per iteration (MLP=2) -----------------
    const int nthreads = gridDim.x * blockDim.x;
    const int base = blockIdx.x * blockDim.x + tid;

    int idx0 = base;
    int idx1 = base + nthreads;
    for (; idx1 < n; idx0 += 2 * nthreads, idx1 += 2 * nthreads) {
        // rows are 32B; load first 16B of each (one 32B sector per row either way)
        float4 r0 = __ldg(reinterpret_cast<const float4*>(x + (size_t)idx0 * 8));
        float4 r1 = __ldg(reinterpret_cast<const float4*>(x + (size_t)idx1 * 8));
        out[idx0] = qform(sM, r0);
        out[idx1] = qform(sM, r1);
    }
    if (idx0 < n) {
        float4 r0 = __ldg(reinterpret_cast<const float4*>(x + (size_t)idx0 * 8));
        out[idx0] = qform(sM, r0);
    }
}

extern "C" void kernel_launch(void* const* d_in, const int* in_sizes, int n_in,
                              void* d_out, int out_size)
{
    const float* x = (const float*)d_in[0];   // [B, 8] f32
    const float* w = (const float*)d_in[1];   // [3, 3, 2] f32
    float* out = (float*)d_out;               // [B, 1] f32

    const int n = in_sizes[0] / 8;
    const int tpb = 256;
    const int blocks = 1184;                  // 8 * 148 SMs; ~1.7 iter/thread at MLP=2
    vqc_kernel<<<blocks, tpb>>>(x, w, out, n);
}

// round 4
// speedup vs baseline: 1.4669x; 1.4669x over previous
#include <cuda_runtime.h>
#include <cuda_bf16.h>

// ---------------------------------------------------------------------------
// QuantumLayerVQC reduced to a trilinear form:
//   out[b] = sum_{a,b,c in {0,1,2}} T[a][b][c] * g0[a]*g1[b]*g2[c]
//   g_q = (1, cos x_q, sin x_q)
// T is derived once per block from M (the 8x8 quadratic form of the fixed
// variational unitary U) via half-angle identities:
//   c^2 = (1+cos)/2,  c*s = sin/2,  s^2 = (1-cos)/2.
// Qubit q <-> bitmask (4 >> q): q0->4, q1->2, q2->1.
// ---------------------------------------------------------------------------

__device__ __forceinline__ float2 cmulf(float2 a, float2 b) {
    return make_float2(a.x * b.x - a.y * b.y, a.x * b.y + a.y * b.x);
}

template <int M>
__device__ __forceinline__ void ry_g(float2 st[8], float theta) {
    float s, c;
    __sincosf(0.5f * theta, &s, &c);   // fast path: tiny angles, off hot path
#pragma unroll
    for (int k = 0; k < 8; k++) {
        if (!(k & M)) {
            float2 a = st[k], b = st[k | M];
            st[k]     = make_float2(c * a.x - s * b.x, c * a.y - s * b.y);
            st[k | M] = make_float2(s * a.x + c * b.x, s * a.y + c * b.y);
        }
    }
}

template <int M>
__device__ __forceinline__ void rz_g(float2 st[8], float phi) {
    float s, c;
    __sincosf(0.5f * phi, &s, &c);
    float2 p0 = make_float2(c, -s);
    float2 p1 = make_float2(c,  s);
#pragma unroll
    for (int k = 0; k < 8; k++) st[k] = cmulf(st[k], (k & M) ? p1 : p0);
}

template <int CM, int TM>
__device__ __forceinline__ void cnot_g(float2 st[8]) {
#pragma unroll
    for (int k = 0; k < 8; k++) {
        if ((k & CM) && !(k & TM)) {
            float2 t = st[k];
            st[k] = st[k | TM];
            st[k | TM] = t;
        }
    }
}

// Per-row evaluation: 6 MUFU + ~33 FMA + 27 broadcast LDS
__device__ __forceinline__ float trilinear(const float* __restrict__ sT, float4 r) {
    float c0, s0, c1, s1, c2, s2;
    __sincosf(r.x, &s0, &c0);   // full angles (half-angle fold absorbed into T)
    __sincosf(r.y, &s1, &c1);
    __sincosf(r.z, &s2, &c2);

    const float h11 = c1 * c2, h12 = c1 * s2, h21 = s1 * c2, h22 = s1 * s2;

    float d[3];
#pragma unroll
    for (int a = 0; a < 3; a++) {
        const float* t = sT + a * 9;
        float v = t[0];                 // g1[0]*g2[0] = 1
        v = fmaf(t[1], c2,  v);
        v = fmaf(t[2], s2,  v);
        v = fmaf(t[3], c1,  v);
        v = fmaf(t[4], h11, v);
        v = fmaf(t[5], h12, v);
        v = fmaf(t[6], s1,  v);
        v = fmaf(t[7], h21, v);
        v = fmaf(t[8], h22, v);
        d[a] = v;
    }
    return fmaf(s0, d[2], fmaf(c0, d[1], d[0]));
}

__global__ __launch_bounds__(256, 6) void vqc_kernel(
    const float* __restrict__ x,   // [n, 8]
    const float* __restrict__ w,   // [3, 3, 2]
    float* __restrict__ out,       // [n]
    int n)
{
    __shared__ float2 sU[8][8];    // U[k][col]
    __shared__ float  sM[64];      // quadratic-form matrix
    __shared__ float  sT[27];      // trilinear coefficients

    const int tid = threadIdx.x;

    // --- Phase 1: threads 0..7 simulate one basis column of U each ----------
    if (tid < 8) {
        float2 st[8];
#pragma unroll
        for (int k = 0; k < 8; k++) st[k] = make_float2(0.f, 0.f);
        st[tid] = make_float2(1.f, 0.f);

#pragma unroll
        for (int l = 0; l < 3; l++) {
            const float* wl = w + l * 6;
            ry_g<4>(st, wl[0]); rz_g<4>(st, wl[1]);   // qubit 0
            ry_g<2>(st, wl[2]); rz_g<2>(st, wl[3]);   // qubit 1
            ry_g<1>(st, wl[4]); rz_g<1>(st, wl[5]);   // qubit 2
            cnot_g<4, 2>(st);
            cnot_g<2, 1>(st);
        }
#pragma unroll
        for (int k = 0; k < 8; k++) sU[k][tid] = st[k];
    }
    __syncthreads();

    // --- Phase 2: threads 0..63 build M --------------------------------------
    if (tid < 64) {
        const int i = tid >> 3, j = tid & 7;
        float m = 0.f;
#pragma unroll
        for (int k = 0; k < 8; k++) {
            float t = sU[k][i].x * sU[k][j].x + sU[k][i].y * sU[k][j].y;
            m += (k & 4) ? -t : t;
        }
        sM[tid] = m;
    }
    __syncthreads();

    // --- Phase 2b: threads 0..26 build T (basis change per qubit) -----------
    // pair p = i_bit*2 + j_bit -> weights in (1, cos, sin) basis
    if (tid < 27) {
        const float W[4][3] = {
            {0.5f,  0.5f, 0.0f},   // (0,0): c'c' = (1+cos)/2
            {0.0f,  0.0f, 0.5f},   // (0,1): c's' = sin/2
            {0.0f,  0.0f, 0.5f},   // (1,0)
            {0.5f, -0.5f, 0.0f},   // (1,1): s's' = (1-cos)/2
        };
        const int a = tid / 9, b = (tid / 3) % 3, c = tid % 3;
        float acc = 0.f;
#pragma unroll
        for (int i = 0; i < 8; i++) {
#pragma unroll
            for (int j = 0; j < 8; j++) {
                const int p0 = (((i >> 2) & 1) << 1) | ((j >> 2) & 1);
                const int p1 = (((i >> 1) & 1) << 1) | ((j >> 1) & 1);
                const int p2 = ((i & 1) << 1) | (j & 1);
                acc += sM[i * 8 + j] * W[p0][a] * W[p1][b] * W[p2][c];
            }
        }
        sT[tid] = acc;
    }
    __syncthreads();

    // --- Phase 3: grid-stride streaming, 2 rows/iter (MLP=2) ----------------
    const int nthreads = gridDim.x * blockDim.x;
    const int base = blockIdx.x * blockDim.x + tid;

    int idx0 = base;
    int idx1 = base + nthreads;
    for (; idx1 < n; idx0 += 2 * nthreads, idx1 += 2 * nthreads) {
        float4 r0 = __ldg(reinterpret_cast<const float4*>(x + (size_t)idx0 * 8));
        float4 r1 = __ldg(reinterpret_cast<const float4*>(x + (size_t)idx1 * 8));
        out[idx0] = trilinear(sT, r0);
        out[idx1] = trilinear(sT, r1);
    }
    if (idx0 < n) {
        float4 r0 = __ldg(reinterpret_cast<const float4*>(x + (size_t)idx0 * 8));
        out[idx0] = trilinear(sT, r0);
    }
}

extern "C" void kernel_launch(void* const* d_in, const int* in_sizes, int n_in,
                              void* d_out, int out_size)
{
    const float* x = (const float*)d_in[0];   // [B, 8] f32
    const float* w = (const float*)d_in[1];   // [3, 3, 2] f32
    float* out = (float*)d_out;               // [B, 1] f32

    const int n = in_sizes[0] / 8;
    const int tpb = 256;
    const int blocks = 888;                   // 6 CTAs/SM * 148 SMs = one full wave
    vqc_kernel<<<blocks, tpb>>>(x, w, out, n);
}